// round 2
// baseline (speedup 1.0000x reference)
#include <cuda_runtime.h>
#include <cuda_bf16.h>

// Problem constants
#define NMAX 100000
#define EMAX 1600000

// ---------------- scratch (static device globals; no runtime alloc) ----------------
static __device__ __align__(16) float g_sup [ (size_t)NMAX*128 ];
static __device__ __align__(16) float g_h   [ (size_t)NMAX*128 ];
static __device__ __align__(16) float g_sup2[ (size_t)NMAX*64  ];
static __device__ __align__(16) float g_x1  [ (size_t)NMAX*64  ];
static __device__ __align__(16) float g_x2  [ (size_t)NMAX*64  ];
static __device__ __align__(16) float g_av  [ NMAX ];
static __device__ __align__(16) float g_bv  [ NMAX ];
static __device__ __align__(16) float g_wc  [ 132 ];      // w[0..127], c at [128]
static __device__ __align__(16) int   g_rp_o[ NMAX+1 ];
static __device__ __align__(16) int   g_rp_s[ NMAX+1 ];
static __device__ __align__(16) int   g_srcO[ EMAX ];
static __device__ __align__(16) int   g_srcS[ EMAX ];
static __device__ __align__(16) float g_valO[ EMAX ];
static __device__ __align__(16) float g_valS[ EMAX ];
static __device__ __align__(16) int   g_cur [ NMAX ];
static __device__ __align__(16) int   g_bsum[ 128 ];
static __device__ __align__(16) int   g_boff[ 128 ];
static __device__            int   g_i64flag;

// ---------------- idx dtype detection ----------------
// If idx is int64 with small non-negative values, every odd 32-bit word (the
// high halves) is zero. If idx is int32, odd words are random node ids.
__global__ void k_detect(const int* __restrict__ idx32, int nwords) {
    // single warp
    int t = threadIdx.x;       // 32 threads, each checks 4 odd words
    int bad = 0;
#pragma unroll
    for (int j = 0; j < 4; ++j) {
        int w = (t * 4 + j) * 2 + 1;
        if (w < nwords && idx32[w] != 0) bad = 1;
    }
    unsigned m = __ballot_sync(0xFFFFFFFFu, bad);
    if (t == 0) g_i64flag = (m == 0u) ? 1 : 0;
}

// ---------------- CSR build ----------------
__global__ void k_hist(const int* __restrict__ dst, int* __restrict__ cnt, int E) {
    int i = blockIdx.x * blockDim.x + threadIdx.x;
    if (i < E) atomicAdd(&cnt[dst[i]], 1);
}

// chunked exclusive scan, CHUNK = 1024 (256 thr x 4)
__global__ void k_scan1(const int* __restrict__ cnt, int* __restrict__ out,
                        int* __restrict__ bsum, int n) {
    __shared__ int s[256];
    int t = threadIdx.x;
    int base = blockIdx.x * 1024;
    int v[4]; int sum = 0;
#pragma unroll
    for (int j = 0; j < 4; ++j) {
        int i = base + t * 4 + j;
        v[j] = (i < n) ? cnt[i] : 0;
        sum += v[j];
    }
    s[t] = sum; __syncthreads();
    for (int off = 1; off < 256; off <<= 1) {
        int x = (t >= off) ? s[t - off] : 0;
        __syncthreads();
        s[t] += x;
        __syncthreads();
    }
    int run = s[t] - sum;     // exclusive within chunk
    if (t == 255) bsum[blockIdx.x] = s[255];
#pragma unroll
    for (int j = 0; j < 4; ++j) {
        int i = base + t * 4 + j;
        if (i < n) out[i] = run;
        run += v[j];
    }
}

__global__ void k_scan2(const int* __restrict__ bsum, int* __restrict__ boff, int nb) {
    __shared__ int s[128];
    int t = threadIdx.x;
    int v = (t < nb) ? bsum[t] : 0;
    s[t] = v; __syncthreads();
    for (int off = 1; off < 128; off <<= 1) {
        int x = (t >= off) ? s[t - off] : 0;
        __syncthreads();
        s[t] += x;
        __syncthreads();
    }
    if (t < nb) boff[t] = s[t] - v;
}

__global__ void k_scan3(int* __restrict__ rp, const int* __restrict__ boff,
                        int* __restrict__ cur, int n, int E) {
    int i = blockIdx.x * blockDim.x + threadIdx.x;
    if (i < n) {
        int v = rp[i] + boff[i >> 10];
        rp[i] = v;
        cur[i] = v;
    } else if (i == n) {
        rp[n] = E;
    }
}

__global__ void k_scatter(const int* __restrict__ dst, const int* __restrict__ srcI,
                          const float* __restrict__ valI, int* __restrict__ cur,
                          int* __restrict__ csrc, float* __restrict__ cval, int E) {
    int e = blockIdx.x * blockDim.x + threadIdx.x;
    if (e < E) {
        int d = dst[e];
        int p = atomicAdd(&cur[d], 1);
        csrc[p] = srcI[e];
        cval[p] = valI[e];
    }
}

// ---------------- GEMMs (fp32, smem-tiled) ----------------
// C[M,128] = A[M,128] @ B[128,128]
__global__ void k_gemm_n128(const float* __restrict__ A, const float* __restrict__ B,
                            float* __restrict__ C, int M) {
    __shared__ float sA[64][64];
    __shared__ float sB[64][128];
    const int tid = threadIdx.x;       // 256
    const int cg  = tid & 31;          // 4 cols each -> 128 cols
    const int rg  = tid >> 5;          // 8 rows each -> 64 rows
    const int row0 = blockIdx.x * 64;
    float acc[8][4];
#pragma unroll
    for (int r = 0; r < 8; ++r) { acc[r][0]=0.f; acc[r][1]=0.f; acc[r][2]=0.f; acc[r][3]=0.f; }

    for (int kc = 0; kc < 2; ++kc) {
#pragma unroll
        for (int i = 0; i < 4; ++i) {
            int idx = i * 256 + tid;
            int r = idx >> 4, kk = (idx & 15) << 2;
            float4 v = make_float4(0.f, 0.f, 0.f, 0.f);
            int gr = row0 + r;
            if (gr < M) v = *(const float4*)(A + (size_t)gr * 128 + kc * 64 + kk);
            *(float4*)&sA[r][kk] = v;
        }
#pragma unroll
        for (int i = 0; i < 8; ++i) {
            int idx = i * 256 + tid;
            int kk = idx >> 5, cc = (idx & 31) << 2;
            *(float4*)&sB[kk][cc] = *(const float4*)(B + (size_t)(kc * 64 + kk) * 128 + cc);
        }
        __syncthreads();
#pragma unroll 8
        for (int k = 0; k < 64; ++k) {
            float4 bv = *(const float4*)&sB[k][cg * 4];
#pragma unroll
            for (int r = 0; r < 8; ++r) {
                float av = sA[rg * 8 + r][k];
                acc[r][0] = fmaf(av, bv.x, acc[r][0]);
                acc[r][1] = fmaf(av, bv.y, acc[r][1]);
                acc[r][2] = fmaf(av, bv.z, acc[r][2]);
                acc[r][3] = fmaf(av, bv.w, acc[r][3]);
            }
        }
        __syncthreads();
    }
#pragma unroll
    for (int r = 0; r < 8; ++r) {
        int gr = row0 + rg * 8 + r;
        if (gr < M)
            *(float4*)(C + (size_t)gr * 128 + cg * 4) =
                make_float4(acc[r][0], acc[r][1], acc[r][2], acc[r][3]);
    }
}

// C[M,64] = A[M,128] @ B[128,64]
__global__ void k_gemm_n64(const float* __restrict__ A, const float* __restrict__ B,
                           float* __restrict__ C, int M) {
    __shared__ float sA[64][64];
    __shared__ float sB[64][64];
    const int tid = threadIdx.x;       // 256
    const int cg  = tid & 31;          // 2 cols each -> 64 cols
    const int rg  = tid >> 5;          // 8 rows each -> 64 rows
    const int row0 = blockIdx.x * 64;
    float acc[8][2];
#pragma unroll
    for (int r = 0; r < 8; ++r) { acc[r][0] = 0.f; acc[r][1] = 0.f; }

    for (int kc = 0; kc < 2; ++kc) {
#pragma unroll
        for (int i = 0; i < 4; ++i) {
            int idx = i * 256 + tid;
            int r = idx >> 4, kk = (idx & 15) << 2;
            float4 v = make_float4(0.f, 0.f, 0.f, 0.f);
            int gr = row0 + r;
            if (gr < M) v = *(const float4*)(A + (size_t)gr * 128 + kc * 64 + kk);
            *(float4*)&sA[r][kk] = v;
        }
#pragma unroll
        for (int i = 0; i < 4; ++i) {
            int idx = i * 256 + tid;
            int kk = idx >> 4, cc = (idx & 15) << 2;
            *(float4*)&sB[kk][cc] = *(const float4*)(B + (size_t)(kc * 64 + kk) * 64 + cc);
        }
        __syncthreads();
#pragma unroll 8
        for (int k = 0; k < 64; ++k) {
            float2 bv = *(const float2*)&sB[k][cg * 2];
#pragma unroll
            for (int r = 0; r < 8; ++r) {
                float av = sA[rg * 8 + r][k];
                acc[r][0] = fmaf(av, bv.x, acc[r][0]);
                acc[r][1] = fmaf(av, bv.y, acc[r][1]);
            }
        }
        __syncthreads();
    }
#pragma unroll
    for (int r = 0; r < 8; ++r) {
        int gr = row0 + rg * 8 + r;
        if (gr < M)
            *(float2*)(C + (size_t)gr * 64 + cg * 2) = make_float2(acc[r][0], acc[r][1]);
    }
}

// ---------------- SpMM (CSR, gather + register accumulate) ----------------
__global__ void k_spmm_w128(const int* __restrict__ rp, const int* __restrict__ src,
                            const float* __restrict__ val, const float* __restrict__ sup,
                            const float* __restrict__ bias, float* __restrict__ out,
                            int M, int relu) {
    int w = (blockIdx.x * blockDim.x + threadIdx.x) >> 5;
    if (w >= M) return;
    int l = threadIdx.x & 31;
    float4 acc = *(const float4*)(bias + l * 4);
    int p = rp[w], e = rp[w + 1];
    for (; p + 1 < e; p += 2) {
        int   s0 = __ldg(&src[p]),     s1 = __ldg(&src[p + 1]);
        float v0 = __ldg(&val[p]),     v1 = __ldg(&val[p + 1]);
        float4 m0 = *(const float4*)(sup + (size_t)s0 * 128 + l * 4);
        float4 m1 = *(const float4*)(sup + (size_t)s1 * 128 + l * 4);
        acc.x = fmaf(v0, m0.x, fmaf(v1, m1.x, acc.x));
        acc.y = fmaf(v0, m0.y, fmaf(v1, m1.y, acc.y));
        acc.z = fmaf(v0, m0.z, fmaf(v1, m1.z, acc.z));
        acc.w = fmaf(v0, m0.w, fmaf(v1, m1.w, acc.w));
    }
    if (p < e) {
        int s0 = __ldg(&src[p]); float v0 = __ldg(&val[p]);
        float4 m0 = *(const float4*)(sup + (size_t)s0 * 128 + l * 4);
        acc.x = fmaf(v0, m0.x, acc.x); acc.y = fmaf(v0, m0.y, acc.y);
        acc.z = fmaf(v0, m0.z, acc.z); acc.w = fmaf(v0, m0.w, acc.w);
    }
    if (relu) {
        acc.x = fmaxf(acc.x, 0.f); acc.y = fmaxf(acc.y, 0.f);
        acc.z = fmaxf(acc.z, 0.f); acc.w = fmaxf(acc.w, 0.f);
    }
    *(float4*)(out + (size_t)w * 128 + l * 4) = acc;
}

__global__ void k_spmm_w64(const int* __restrict__ rp, const int* __restrict__ src,
                           const float* __restrict__ val, const float* __restrict__ sup,
                           const float* __restrict__ bias, float* __restrict__ out,
                           int M) {
    int w = (blockIdx.x * blockDim.x + threadIdx.x) >> 5;
    if (w >= M) return;
    int l = threadIdx.x & 31;
    float2 acc = *(const float2*)(bias + l * 2);
    int p = rp[w], e = rp[w + 1];
    for (; p + 1 < e; p += 2) {
        int   s0 = __ldg(&src[p]),     s1 = __ldg(&src[p + 1]);
        float v0 = __ldg(&val[p]),     v1 = __ldg(&val[p + 1]);
        float2 m0 = *(const float2*)(sup + (size_t)s0 * 64 + l * 2);
        float2 m1 = *(const float2*)(sup + (size_t)s1 * 64 + l * 2);
        acc.x = fmaf(v0, m0.x, fmaf(v1, m1.x, acc.x));
        acc.y = fmaf(v0, m0.y, fmaf(v1, m1.y, acc.y));
    }
    if (p < e) {
        int s0 = __ldg(&src[p]); float v0 = __ldg(&val[p]);
        float2 m0 = *(const float2*)(sup + (size_t)s0 * 64 + l * 2);
        acc.x = fmaf(v0, m0.x, acc.x); acc.y = fmaf(v0, m0.y, acc.y);
    }
    *(float2*)(out + (size_t)w * 64 + l * 2) = acc;
}

// ---------------- decoder fold ----------------
__global__ void k_prep(const float* __restrict__ d1W, const float* __restrict__ d1b,
                       const float* __restrict__ d2W, const float* __restrict__ d2b,
                       float* __restrict__ wc) {
    int k = threadIdx.x;     // 128
    float s = 0.f;
#pragma unroll 8
    for (int j = 0; j < 64; ++j) s = fmaf(d1W[k * 64 + j], d2W[j], s);
    wc[k] = s;
    if (k == 0) {
        float c = d2b[0];
        for (int j = 0; j < 64; ++j) c = fmaf(d1b[j], d2W[j], c);
        wc[128] = c;
    }
}

// ---------------- gating + per-node decode scalars ----------------
__global__ void k_gate(const float* __restrict__ x1, const float* __restrict__ x2,
                       const float* __restrict__ ag1, const float* __restrict__ ag2,
                       const float* __restrict__ wc, float* __restrict__ ga,
                       float* __restrict__ gb, int N) {
    int w = (blockIdx.x * blockDim.x + threadIdx.x) >> 5;
    if (w >= N) return;
    int l = threadIdx.x & 31;
    float2 v1 = *(const float2*)(x1 + (size_t)w * 64 + l * 2);
    float2 v2 = *(const float2*)(x2 + (size_t)w * 64 + l * 2);
    float2 a1 = *(const float2*)(ag1 + l * 2);
    float2 a2 = *(const float2*)(ag2 + l * 2);
    float g1 = v1.x * a1.x + v1.y * a1.y;
    float g2 = v2.x * a2.x + v2.y * a2.y;
#pragma unroll
    for (int o = 16; o > 0; o >>= 1) {
        g1 += __shfl_xor_sync(0xFFFFFFFFu, g1, o);
        g2 += __shfl_xor_sync(0xFFFFFFFFu, g2, o);
    }
    float gx = g1 * v1.x + g2 * v2.x;
    float gy = g1 * v1.y + g2 * v2.y;
    float2 wl = *(const float2*)(wc + l * 2);
    float2 wh = *(const float2*)(wc + 64 + l * 2);
    float av = gx * wl.x + gy * wl.y;
    float bv = gx * wh.x + gy * wh.y;
#pragma unroll
    for (int o = 16; o > 0; o >>= 1) {
        av += __shfl_xor_sync(0xFFFFFFFFu, av, o);
        bv += __shfl_xor_sync(0xFFFFFFFFu, bv, o);
    }
    if (l == 0) { ga[w] = av; gb[w] = bv; }
}

// ---------------- pair output: out[p] = a[i0] + b[i1] + c ----------------
__global__ void k_final(const void* __restrict__ idxv, const float* __restrict__ ga,
                        const float* __restrict__ gb, const float* __restrict__ wc,
                        float* __restrict__ out, int P, int N) {
    int p = blockIdx.x * blockDim.x + threadIdx.x;
    if (p >= P) return;
    long long i0, i1;
    if (g_i64flag) {
        const long long* q = (const long long*)idxv;
        i0 = q[p]; i1 = q[(size_t)P + p];
    } else {
        const int* q = (const int*)idxv;
        i0 = q[p]; i1 = q[(size_t)P + p];
    }
    // safety clamp: wrong dtype guess degrades to rel_err, not a crash
    i0 = i0 < 0 ? 0 : (i0 >= N ? N - 1 : i0);
    i1 = i1 < 0 ? 0 : (i1 >= N ? N - 1 : i1);
    out[p] = ga[i0] + gb[i1] + wc[128];
}

// ---------------- host ----------------
extern "C" void kernel_launch(void* const* d_in, const int* in_sizes, int n_in,
                              void* d_out, int out_size) {
    const float* x       = (const float*)d_in[0];
    const int*   o_edges = (const int*)d_in[1];
    const float* o_vals  = (const float*)d_in[2];
    const int*   s_edges = (const int*)d_in[3];
    const float* s_vals  = (const float*)d_in[4];
    const void*  idx     = d_in[5];
    const float* W_o1 = (const float*)d_in[6];
    const float* b_o1 = (const float*)d_in[7];
    const float* W_o2 = (const float*)d_in[8];
    const float* b_o2 = (const float*)d_in[9];
    const float* W_s1 = (const float*)d_in[10];
    const float* b_s1 = (const float*)d_in[11];
    const float* W_s2 = (const float*)d_in[12];
    const float* b_s2 = (const float*)d_in[13];
    const float* ag1  = (const float*)d_in[14];
    const float* ag2  = (const float*)d_in[15];
    const float* d1W  = (const float*)d_in[16];
    const float* d1b  = (const float*)d_in[17];
    const float* d2W  = (const float*)d_in[18];
    const float* d2b  = (const float*)d_in[19];
    float* out = (float*)d_out;

    const int N = in_sizes[0] / 128;
    const int E = in_sizes[2];
    const int P = in_sizes[5] / 2;

    float *sup, *h, *sup2, *x1b, *x2b, *ga, *gb, *wc, *valO, *valS;
    int *rpO, *rpS, *srcO, *srcS, *cur, *bsum, *boff;
    cudaGetSymbolAddress((void**)&sup,  g_sup);
    cudaGetSymbolAddress((void**)&h,    g_h);
    cudaGetSymbolAddress((void**)&sup2, g_sup2);
    cudaGetSymbolAddress((void**)&x1b,  g_x1);
    cudaGetSymbolAddress((void**)&x2b,  g_x2);
    cudaGetSymbolAddress((void**)&ga,   g_av);
    cudaGetSymbolAddress((void**)&gb,   g_bv);
    cudaGetSymbolAddress((void**)&wc,   g_wc);
    cudaGetSymbolAddress((void**)&rpO,  g_rp_o);
    cudaGetSymbolAddress((void**)&rpS,  g_rp_s);
    cudaGetSymbolAddress((void**)&srcO, g_srcO);
    cudaGetSymbolAddress((void**)&srcS, g_srcS);
    cudaGetSymbolAddress((void**)&valO, g_valO);
    cudaGetSymbolAddress((void**)&valS, g_valS);
    cudaGetSymbolAddress((void**)&cur,  g_cur);
    cudaGetSymbolAddress((void**)&bsum, g_bsum);
    cudaGetSymbolAddress((void**)&boff, g_boff);

    const int nb = (N + 1023) / 1024;

    // idx dtype detection (cheap, deterministic)
    {
        int nwords = in_sizes[5];   // element count; if int64, 32-bit words = 2x,
                                    // but we only probe within min bound below
        // probe only within the first 2*128 32-bit words, safe for either dtype
        int probe = nwords < 256 ? nwords : 256;
        k_detect<<<1, 32>>>((const int*)idx, probe);
    }

    // decoder fold (independent)
    k_prep<<<1, 128>>>(d1W, d1b, d2W, d2b, wc);

    // CSR build for both adjacencies
    {
        const int* dst  = o_edges;
        const int* srcI = o_edges + E;
        cudaMemsetAsync(rpO, 0, (size_t)N * sizeof(int), 0);
        k_hist<<<(E + 255) / 256, 256>>>(dst, rpO, E);
        k_scan1<<<nb, 256>>>(rpO, rpO, bsum, N);
        k_scan2<<<1, 128>>>(bsum, boff, nb);
        k_scan3<<<(N + 1 + 255) / 256, 256>>>(rpO, boff, cur, N, E);
        k_scatter<<<(E + 255) / 256, 256>>>(dst, srcI, o_vals, cur, srcO, valO, E);
    }
    {
        const int* dst  = s_edges;
        const int* srcI = s_edges + E;
        cudaMemsetAsync(rpS, 0, (size_t)N * sizeof(int), 0);
        k_hist<<<(E + 255) / 256, 256>>>(dst, rpS, E);
        k_scan1<<<nb, 256>>>(rpS, rpS, bsum, N);
        k_scan2<<<1, 128>>>(bsum, boff, nb);
        k_scan3<<<(N + 1 + 255) / 256, 256>>>(rpS, boff, cur, N, E);
        k_scatter<<<(E + 255) / 256, 256>>>(dst, srcI, s_vals, cur, srcS, valS, E);
    }

    const int gemm_grid = (N + 63) / 64;
    const int spmm_grid = (N * 32 + 255) / 256;

    // branch o
    k_gemm_n128<<<gemm_grid, 256>>>(x, W_o1, sup, N);
    k_spmm_w128<<<spmm_grid, 256>>>(rpO, srcO, valO, sup, b_o1, h, N, 1);
    k_gemm_n64 <<<gemm_grid, 256>>>(h, W_o2, sup2, N);
    k_spmm_w64 <<<spmm_grid, 256>>>(rpO, srcO, valO, sup2, b_o2, x1b, N);

    // branch s
    k_gemm_n128<<<gemm_grid, 256>>>(x, W_s1, sup, N);
    k_spmm_w128<<<spmm_grid, 256>>>(rpS, srcS, valS, sup, b_s1, h, N, 1);
    k_gemm_n64 <<<gemm_grid, 256>>>(h, W_s2, sup2, N);
    k_spmm_w64 <<<spmm_grid, 256>>>(rpS, srcS, valS, sup2, b_s2, x2b, N);

    // gate + per-node decode scalars, then pair gather
    k_gate<<<spmm_grid, 256>>>(x1b, x2b, ag1, ag2, wc, ga, gb, N);
    k_final<<<(P + 255) / 256, 256>>>(idx, ga, gb, wc, out, P, N);
}

// round 3
// speedup vs baseline: 1.3738x; 1.3738x over previous
#include <cuda_runtime.h>
#include <cuda_bf16.h>

// Problem constants
#define NMAX 100000
#define EMAX 1600000

// ---------------- scratch (static device globals; no runtime alloc) ----------------
static __device__ __align__(16) float g_sup [ (size_t)NMAX*128 ];
static __device__ __align__(16) float g_h   [ (size_t)NMAX*128 ];
static __device__ __align__(16) float g_sup2[ (size_t)NMAX*64  ];
static __device__ __align__(16) float g_x1  [ (size_t)NMAX*64  ];
static __device__ __align__(16) float g_x2  [ (size_t)NMAX*64  ];
static __device__ __align__(16) float g_av  [ NMAX ];
static __device__ __align__(16) float g_bv  [ NMAX ];
static __device__ __align__(16) float g_wc  [ 132 ];      // w[0..127], c at [128]
static __device__ __align__(16) int   g_rp_o[ NMAX+1 ];
static __device__ __align__(16) int   g_rp_s[ NMAX+1 ];
static __device__ __align__(16) int   g_srcO[ EMAX ];
static __device__ __align__(16) int   g_srcS[ EMAX ];
static __device__ __align__(16) float g_valO[ EMAX ];
static __device__ __align__(16) float g_valS[ EMAX ];
static __device__ __align__(16) int   g_cur [ NMAX ];
static __device__ __align__(16) int   g_bsum[ 128 ];
static __device__ __align__(16) int   g_boff[ 128 ];
static __device__            int   g_i64flag;

// ---------------- idx dtype detection ----------------
__global__ void k_detect(const int* __restrict__ idx32, int nwords) {
    int t = threadIdx.x;
    int bad = 0;
#pragma unroll
    for (int j = 0; j < 4; ++j) {
        int w = (t * 4 + j) * 2 + 1;
        if (w < nwords && idx32[w] != 0) bad = 1;
    }
    unsigned m = __ballot_sync(0xFFFFFFFFu, bad);
    if (t == 0) g_i64flag = (m == 0u) ? 1 : 0;
}

// ---------------- CSR build ----------------
__global__ void k_hist(const int* __restrict__ dst, int* __restrict__ cnt, int E) {
    int i = blockIdx.x * blockDim.x + threadIdx.x;
    if (i < E) atomicAdd(&cnt[dst[i]], 1);
}

__global__ void k_scan1(const int* __restrict__ cnt, int* __restrict__ out,
                        int* __restrict__ bsum, int n) {
    __shared__ int s[256];
    int t = threadIdx.x;
    int base = blockIdx.x * 1024;
    int v[4]; int sum = 0;
#pragma unroll
    for (int j = 0; j < 4; ++j) {
        int i = base + t * 4 + j;
        v[j] = (i < n) ? cnt[i] : 0;
        sum += v[j];
    }
    s[t] = sum; __syncthreads();
    for (int off = 1; off < 256; off <<= 1) {
        int x = (t >= off) ? s[t - off] : 0;
        __syncthreads();
        s[t] += x;
        __syncthreads();
    }
    int run = s[t] - sum;
    if (t == 255) bsum[blockIdx.x] = s[255];
#pragma unroll
    for (int j = 0; j < 4; ++j) {
        int i = base + t * 4 + j;
        if (i < n) out[i] = run;
        run += v[j];
    }
}

__global__ void k_scan2(const int* __restrict__ bsum, int* __restrict__ boff, int nb) {
    __shared__ int s[128];
    int t = threadIdx.x;
    int v = (t < nb) ? bsum[t] : 0;
    s[t] = v; __syncthreads();
    for (int off = 1; off < 128; off <<= 1) {
        int x = (t >= off) ? s[t - off] : 0;
        __syncthreads();
        s[t] += x;
        __syncthreads();
    }
    if (t < nb) boff[t] = s[t] - v;
}

__global__ void k_scan3(int* __restrict__ rp, const int* __restrict__ boff,
                        int* __restrict__ cur, int n, int E) {
    int i = blockIdx.x * blockDim.x + threadIdx.x;
    if (i < n) {
        int v = rp[i] + boff[i >> 10];
        rp[i] = v;
        cur[i] = v;
    } else if (i == n) {
        rp[n] = E;
    }
}

__global__ void k_scatter(const int* __restrict__ dst, const int* __restrict__ srcI,
                          const float* __restrict__ valI, int* __restrict__ cur,
                          int* __restrict__ csrc, float* __restrict__ cval, int E) {
    int e = blockIdx.x * blockDim.x + threadIdx.x;
    if (e < E) {
        int d = dst[e];
        int p = atomicAdd(&cur[d], 1);
        csrc[p] = srcI[e];
        cval[p] = valI[e];
    }
}

// ---------------- GEMM via tf32 tensor cores ----------------
// C[M,BN] = A[M,128] @ B[128,BN]; BM=128 tile, 8 warps, cp.async 2-stage, BK=16.
template<int BN>
__global__ __launch_bounds__(256, 2)
void k_gemm_tf32(const float* __restrict__ A, const float* __restrict__ B,
                 float* __restrict__ C, int M) {
    constexpr int BM = 128, BK = 16, KTOT = 128, NCH = KTOT / BK;
    constexpr int WN = BN / 2;       // warp n-extent (64 or 32)
    constexpr int NT = WN / 8;       // n-tiles per warp (8 or 4)
    __shared__ float sA[2][BM][BK + 4];    // pad 4 -> conflict-free frag loads
    __shared__ float sB[2][BK][BN + 8];    // pad 8 -> conflict-free frag loads
    const int tid  = threadIdx.x;
    const int wid  = tid >> 5, lane = tid & 31;
    const int wm   = wid & 3,  wn   = wid >> 2;
    const int g    = lane >> 2, tig = lane & 3;
    const int row0 = blockIdx.x * BM;

    float acc[2][NT][4];
#pragma unroll
    for (int mt = 0; mt < 2; ++mt)
#pragma unroll
        for (int nt = 0; nt < NT; ++nt)
#pragma unroll
            for (int i = 0; i < 4; ++i) acc[mt][nt][i] = 0.f;

    auto loadA = [&](int ck, int s) {
#pragma unroll
        for (int i = 0; i < 2; ++i) {          // 512 float4 / 256 threads
            int idx = i * 256 + tid;
            int r = idx >> 2, c4 = idx & 3;    // 4 float4 per row (BK=16)
            const float* gp = A + (size_t)(row0 + r) * KTOT + ck * BK + c4 * 4;
            unsigned sp = (unsigned)__cvta_generic_to_shared(&sA[s][r][c4 * 4]);
            int bytes = (row0 + r < M) ? 16 : 0;   // zero-fill OOB rows
            asm volatile("cp.async.cg.shared.global [%0], [%1], 16, %2;\n"
                         :: "r"(sp), "l"(gp), "r"(bytes));
        }
    };
    auto loadB = [&](int ck, int s) {
        constexpr int F4 = BK * BN / 4;        // 512 (BN=128) or 256 (BN=64)
#pragma unroll
        for (int i = 0; i < F4 / 256; ++i) {
            int idx = i * 256 + tid;
            int r = idx / (BN / 4), c4 = idx % (BN / 4);
            const float* gp = B + (size_t)(ck * BK + r) * BN + c4 * 4;
            unsigned sp = (unsigned)__cvta_generic_to_shared(&sB[s][r][c4 * 4]);
            asm volatile("cp.async.cg.shared.global [%0], [%1], 16, 16;\n"
                         :: "r"(sp), "l"(gp));
        }
    };

    auto compute = [&](int s) {
#pragma unroll
        for (int ks = 0; ks < BK / 8; ++ks) {
            unsigned af[2][4];
#pragma unroll
            for (int mt = 0; mt < 2; ++mt) {
                int r = wm * 32 + mt * 16 + g;
                float x0 = sA[s][r    ][ks * 8 + tig    ];
                float x1 = sA[s][r + 8][ks * 8 + tig    ];
                float x2 = sA[s][r    ][ks * 8 + tig + 4];
                float x3 = sA[s][r + 8][ks * 8 + tig + 4];
                asm("cvt.rna.tf32.f32 %0, %1;" : "=r"(af[mt][0]) : "f"(x0));
                asm("cvt.rna.tf32.f32 %0, %1;" : "=r"(af[mt][1]) : "f"(x1));
                asm("cvt.rna.tf32.f32 %0, %1;" : "=r"(af[mt][2]) : "f"(x2));
                asm("cvt.rna.tf32.f32 %0, %1;" : "=r"(af[mt][3]) : "f"(x3));
            }
            unsigned bf[NT][2];
#pragma unroll
            for (int nt = 0; nt < NT; ++nt) {
                int c = wn * WN + nt * 8 + g;
                float y0 = sB[s][ks * 8 + tig    ][c];
                float y1 = sB[s][ks * 8 + tig + 4][c];
                asm("cvt.rna.tf32.f32 %0, %1;" : "=r"(bf[nt][0]) : "f"(y0));
                asm("cvt.rna.tf32.f32 %0, %1;" : "=r"(bf[nt][1]) : "f"(y1));
            }
#pragma unroll
            for (int mt = 0; mt < 2; ++mt)
#pragma unroll
                for (int nt = 0; nt < NT; ++nt)
                    asm volatile(
                        "mma.sync.aligned.m16n8k8.row.col.f32.tf32.tf32.f32 "
                        "{%0,%1,%2,%3}, {%4,%5,%6,%7}, {%8,%9}, {%0,%1,%2,%3};\n"
                        : "+f"(acc[mt][nt][0]), "+f"(acc[mt][nt][1]),
                          "+f"(acc[mt][nt][2]), "+f"(acc[mt][nt][3])
                        : "r"(af[mt][0]), "r"(af[mt][1]), "r"(af[mt][2]), "r"(af[mt][3]),
                          "r"(bf[nt][0]), "r"(bf[nt][1]));
        }
    };

    loadA(0, 0); loadB(0, 0);
    asm volatile("cp.async.commit_group;\n");
#pragma unroll
    for (int ck = 0; ck < NCH; ++ck) {
        if (ck + 1 < NCH) {
            loadA(ck + 1, (ck + 1) & 1); loadB(ck + 1, (ck + 1) & 1);
            asm volatile("cp.async.commit_group;\n");
            asm volatile("cp.async.wait_group 1;\n");
        } else {
            asm volatile("cp.async.wait_group 0;\n");
        }
        __syncthreads();
        compute(ck & 1);
        __syncthreads();
    }

#pragma unroll
    for (int mt = 0; mt < 2; ++mt) {
        int r = row0 + wm * 32 + mt * 16 + g;
#pragma unroll
        for (int nt = 0; nt < NT; ++nt) {
            int c = wn * WN + nt * 8 + tig * 2;
            if (r < M)
                *(float2*)(C + (size_t)r * BN + c) =
                    make_float2(acc[mt][nt][0], acc[mt][nt][1]);
            if (r + 8 < M)
                *(float2*)(C + (size_t)(r + 8) * BN + c) =
                    make_float2(acc[mt][nt][2], acc[mt][nt][3]);
        }
    }
}

// ---------------- SpMM (CSR, gather + register accumulate) ----------------
__global__ void k_spmm_w128(const int* __restrict__ rp, const int* __restrict__ src,
                            const float* __restrict__ val, const float* __restrict__ sup,
                            const float* __restrict__ bias, float* __restrict__ out,
                            int M, int relu) {
    int w = (blockIdx.x * blockDim.x + threadIdx.x) >> 5;
    if (w >= M) return;
    int l = threadIdx.x & 31;
    float4 acc = *(const float4*)(bias + l * 4);
    int p = rp[w], e = rp[w + 1];
    for (; p + 1 < e; p += 2) {
        int   s0 = __ldg(&src[p]),     s1 = __ldg(&src[p + 1]);
        float v0 = __ldg(&val[p]),     v1 = __ldg(&val[p + 1]);
        float4 m0 = *(const float4*)(sup + (size_t)s0 * 128 + l * 4);
        float4 m1 = *(const float4*)(sup + (size_t)s1 * 128 + l * 4);
        acc.x = fmaf(v0, m0.x, fmaf(v1, m1.x, acc.x));
        acc.y = fmaf(v0, m0.y, fmaf(v1, m1.y, acc.y));
        acc.z = fmaf(v0, m0.z, fmaf(v1, m1.z, acc.z));
        acc.w = fmaf(v0, m0.w, fmaf(v1, m1.w, acc.w));
    }
    if (p < e) {
        int s0 = __ldg(&src[p]); float v0 = __ldg(&val[p]);
        float4 m0 = *(const float4*)(sup + (size_t)s0 * 128 + l * 4);
        acc.x = fmaf(v0, m0.x, acc.x); acc.y = fmaf(v0, m0.y, acc.y);
        acc.z = fmaf(v0, m0.z, acc.z); acc.w = fmaf(v0, m0.w, acc.w);
    }
    if (relu) {
        acc.x = fmaxf(acc.x, 0.f); acc.y = fmaxf(acc.y, 0.f);
        acc.z = fmaxf(acc.z, 0.f); acc.w = fmaxf(acc.w, 0.f);
    }
    *(float4*)(out + (size_t)w * 128 + l * 4) = acc;
}

__global__ void k_spmm_w64(const int* __restrict__ rp, const int* __restrict__ src,
                           const float* __restrict__ val, const float* __restrict__ sup,
                           const float* __restrict__ bias, float* __restrict__ out,
                           int M) {
    int w = (blockIdx.x * blockDim.x + threadIdx.x) >> 5;
    if (w >= M) return;
    int l = threadIdx.x & 31;
    float2 acc = *(const float2*)(bias + l * 2);
    int p = rp[w], e = rp[w + 1];
    for (; p + 1 < e; p += 2) {
        int   s0 = __ldg(&src[p]),     s1 = __ldg(&src[p + 1]);
        float v0 = __ldg(&val[p]),     v1 = __ldg(&val[p + 1]);
        float2 m0 = *(const float2*)(sup + (size_t)s0 * 64 + l * 2);
        float2 m1 = *(const float2*)(sup + (size_t)s1 * 64 + l * 2);
        acc.x = fmaf(v0, m0.x, fmaf(v1, m1.x, acc.x));
        acc.y = fmaf(v0, m0.y, fmaf(v1, m1.y, acc.y));
    }
    if (p < e) {
        int s0 = __ldg(&src[p]); float v0 = __ldg(&val[p]);
        float2 m0 = *(const float2*)(sup + (size_t)s0 * 64 + l * 2);
        acc.x = fmaf(v0, m0.x, acc.x); acc.y = fmaf(v0, m0.y, acc.y);
    }
    *(float2*)(out + (size_t)w * 64 + l * 2) = acc;
}

// ---------------- decoder fold ----------------
__global__ void k_prep(const float* __restrict__ d1W, const float* __restrict__ d1b,
                       const float* __restrict__ d2W, const float* __restrict__ d2b,
                       float* __restrict__ wc) {
    int k = threadIdx.x;     // 128
    float s = 0.f;
#pragma unroll 8
    for (int j = 0; j < 64; ++j) s = fmaf(d1W[k * 64 + j], d2W[j], s);
    wc[k] = s;
    if (k == 0) {
        float c = d2b[0];
        for (int j = 0; j < 64; ++j) c = fmaf(d1b[j], d2W[j], c);
        wc[128] = c;
    }
}

// ---------------- gating + per-node decode scalars ----------------
__global__ void k_gate(const float* __restrict__ x1, const float* __restrict__ x2,
                       const float* __restrict__ ag1, const float* __restrict__ ag2,
                       const float* __restrict__ wc, float* __restrict__ ga,
                       float* __restrict__ gb, int N) {
    int w = (blockIdx.x * blockDim.x + threadIdx.x) >> 5;
    if (w >= N) return;
    int l = threadIdx.x & 31;
    float2 v1 = *(const float2*)(x1 + (size_t)w * 64 + l * 2);
    float2 v2 = *(const float2*)(x2 + (size_t)w * 64 + l * 2);
    float2 a1 = *(const float2*)(ag1 + l * 2);
    float2 a2 = *(const float2*)(ag2 + l * 2);
    float g1 = v1.x * a1.x + v1.y * a1.y;
    float g2 = v2.x * a2.x + v2.y * a2.y;
#pragma unroll
    for (int o = 16; o > 0; o >>= 1) {
        g1 += __shfl_xor_sync(0xFFFFFFFFu, g1, o);
        g2 += __shfl_xor_sync(0xFFFFFFFFu, g2, o);
    }
    float gx = g1 * v1.x + g2 * v2.x;
    float gy = g1 * v1.y + g2 * v2.y;
    float2 wl = *(const float2*)(wc + l * 2);
    float2 wh = *(const float2*)(wc + 64 + l * 2);
    float av = gx * wl.x + gy * wl.y;
    float bv = gx * wh.x + gy * wh.y;
#pragma unroll
    for (int o = 16; o > 0; o >>= 1) {
        av += __shfl_xor_sync(0xFFFFFFFFu, av, o);
        bv += __shfl_xor_sync(0xFFFFFFFFu, bv, o);
    }
    if (l == 0) { ga[w] = av; gb[w] = bv; }
}

// ---------------- pair output ----------------
__global__ void k_final(const void* __restrict__ idxv, const float* __restrict__ ga,
                        const float* __restrict__ gb, const float* __restrict__ wc,
                        float* __restrict__ out, int P, int N) {
    int p = blockIdx.x * blockDim.x + threadIdx.x;
    if (p >= P) return;
    long long i0, i1;
    if (g_i64flag) {
        const long long* q = (const long long*)idxv;
        i0 = q[p]; i1 = q[(size_t)P + p];
    } else {
        const int* q = (const int*)idxv;
        i0 = q[p]; i1 = q[(size_t)P + p];
    }
    i0 = i0 < 0 ? 0 : (i0 >= N ? N - 1 : i0);
    i1 = i1 < 0 ? 0 : (i1 >= N ? N - 1 : i1);
    out[p] = ga[i0] + gb[i1] + wc[128];
}

// ---------------- host ----------------
extern "C" void kernel_launch(void* const* d_in, const int* in_sizes, int n_in,
                              void* d_out, int out_size) {
    const float* x       = (const float*)d_in[0];
    const int*   o_edges = (const int*)d_in[1];
    const float* o_vals  = (const float*)d_in[2];
    const int*   s_edges = (const int*)d_in[3];
    const float* s_vals  = (const float*)d_in[4];
    const void*  idx     = d_in[5];
    const float* W_o1 = (const float*)d_in[6];
    const float* b_o1 = (const float*)d_in[7];
    const float* W_o2 = (const float*)d_in[8];
    const float* b_o2 = (const float*)d_in[9];
    const float* W_s1 = (const float*)d_in[10];
    const float* b_s1 = (const float*)d_in[11];
    const float* W_s2 = (const float*)d_in[12];
    const float* b_s2 = (const float*)d_in[13];
    const float* ag1  = (const float*)d_in[14];
    const float* ag2  = (const float*)d_in[15];
    const float* d1W  = (const float*)d_in[16];
    const float* d1b  = (const float*)d_in[17];
    const float* d2W  = (const float*)d_in[18];
    const float* d2b  = (const float*)d_in[19];
    float* out = (float*)d_out;

    const int N = in_sizes[0] / 128;
    const int E = in_sizes[2];
    const int P = in_sizes[5] / 2;

    float *sup, *h, *sup2, *x1b, *x2b, *ga, *gb, *wc, *valO, *valS;
    int *rpO, *rpS, *srcO, *srcS, *cur, *bsum, *boff;
    cudaGetSymbolAddress((void**)&sup,  g_sup);
    cudaGetSymbolAddress((void**)&h,    g_h);
    cudaGetSymbolAddress((void**)&sup2, g_sup2);
    cudaGetSymbolAddress((void**)&x1b,  g_x1);
    cudaGetSymbolAddress((void**)&x2b,  g_x2);
    cudaGetSymbolAddress((void**)&ga,   g_av);
    cudaGetSymbolAddress((void**)&gb,   g_bv);
    cudaGetSymbolAddress((void**)&wc,   g_wc);
    cudaGetSymbolAddress((void**)&rpO,  g_rp_o);
    cudaGetSymbolAddress((void**)&rpS,  g_rp_s);
    cudaGetSymbolAddress((void**)&srcO, g_srcO);
    cudaGetSymbolAddress((void**)&srcS, g_srcS);
    cudaGetSymbolAddress((void**)&valO, g_valO);
    cudaGetSymbolAddress((void**)&valS, g_valS);
    cudaGetSymbolAddress((void**)&cur,  g_cur);
    cudaGetSymbolAddress((void**)&bsum, g_bsum);
    cudaGetSymbolAddress((void**)&boff, g_boff);

    const int nb = (N + 1023) / 1024;

    {
        int nwords = in_sizes[5];
        int probe = nwords < 256 ? nwords : 256;
        k_detect<<<1, 32>>>((const int*)idx, probe);
    }

    k_prep<<<1, 128>>>(d1W, d1b, d2W, d2b, wc);

    // CSR build for both adjacencies
    {
        const int* dst  = o_edges;
        const int* srcI = o_edges + E;
        cudaMemsetAsync(rpO, 0, (size_t)N * sizeof(int), 0);
        k_hist<<<(E + 255) / 256, 256>>>(dst, rpO, E);
        k_scan1<<<nb, 256>>>(rpO, rpO, bsum, N);
        k_scan2<<<1, 128>>>(bsum, boff, nb);
        k_scan3<<<(N + 1 + 255) / 256, 256>>>(rpO, boff, cur, N, E);
        k_scatter<<<(E + 255) / 256, 256>>>(dst, srcI, o_vals, cur, srcO, valO, E);
    }
    {
        const int* dst  = s_edges;
        const int* srcI = s_edges + E;
        cudaMemsetAsync(rpS, 0, (size_t)N * sizeof(int), 0);
        k_hist<<<(E + 255) / 256, 256>>>(dst, rpS, E);
        k_scan1<<<nb, 256>>>(rpS, rpS, bsum, N);
        k_scan2<<<1, 128>>>(bsum, boff, nb);
        k_scan3<<<(N + 1 + 255) / 256, 256>>>(rpS, boff, cur, N, E);
        k_scatter<<<(E + 255) / 256, 256>>>(dst, srcI, s_vals, cur, srcS, valS, E);
    }

    const int gemm_grid = (N + 127) / 128;
    const int spmm_grid = (N * 32 + 255) / 256;

    // branch o
    k_gemm_tf32<128><<<gemm_grid, 256>>>(x, W_o1, sup, N);
    k_spmm_w128<<<spmm_grid, 256>>>(rpO, srcO, valO, sup, b_o1, h, N, 1);
    k_gemm_tf32<64><<<gemm_grid, 256>>>(h, W_o2, sup2, N);
    k_spmm_w64<<<spmm_grid, 256>>>(rpO, srcO, valO, sup2, b_o2, x1b, N);

    // branch s
    k_gemm_tf32<128><<<gemm_grid, 256>>>(x, W_s1, sup, N);
    k_spmm_w128<<<spmm_grid, 256>>>(rpS, srcS, valS, sup, b_s1, h, N, 1);
    k_gemm_tf32<64><<<gemm_grid, 256>>>(h, W_s2, sup2, N);
    k_spmm_w64<<<spmm_grid, 256>>>(rpS, srcS, valS, sup2, b_s2, x2b, N);

    // gate + per-node decode scalars, then pair gather
    k_gate<<<spmm_grid, 256>>>(x1b, x2b, ag1, ag2, wc, ga, gb, N);
    k_final<<<(P + 255) / 256, 256>>>(idx, ga, gb, wc, out, P, N);
}